// round 1
// baseline (speedup 1.0000x reference)
#include <cuda_runtime.h>
#include <cstdint>

// ---------------------------------------------------------------------------
// IWHT3Layer: 3 branches of
//   y[t, pix, k]  = sum_c x[t, pix, c] * w[t, c, k]        (t = 0..15, 16 coeff GEMMs)
//   out[pix, p, q, k] = (1/16) * sum_{u,v} H[p][u] H[q][v] y[4u+v, pix, k] + bias[k]
// x: [16, 16, 28, 28, 64] fp32, w: [16, 64, 64], bias: [64]
// pixels = 16*28*28 = 12544, output per branch: [16, 112, 112, 64]
//
// Strategy: fused kernel, 32 pixels/block, f32x2 packed FMA (FFMA2) GEMM with
// cp.async double-buffered operand staging; y buffered in smem; in-block
// 2D-WHT butterfly epilogue + bias + scattered coalesced stores.
// Weights pre-interleaved once per launch into __device__ scratch so packed
// operand pairs (along c) load directly with LDS.128, and each warp's w read
// is 256B-contiguous (bank-conflict-free at the 2-cycle data floor).
// ---------------------------------------------------------------------------

#define ULL unsigned long long

static constexpr int PIXELS   = 12544;      // 16*28*28
static constexpr int PIX_T    = 32;         // pixels per block
static constexpr int NBLK     = PIXELS / PIX_T;   // 392
static constexpr int T_STRIDE = PIXELS * 64;      // 802816 floats per coeff plane
static constexpr int OUT_PER_BRANCH = 16 * 112 * 112 * 64; // 12845056

// smem layout (bytes)
static constexpr int Y_BYTES   = PIX_T * 16 * 64 * 4;   // 131072
static constexpr int X_PITCH   = 68 * 4;                // 272 B padded row (conflict-free x)
static constexpr int X_BYTES   = PIX_T * X_PITCH;       // 8704 per buffer
static constexpr int W_BYTES   = 64 * 64 * 4;           // 16384 per buffer
static constexpr int SMEM_BYTES = Y_BYTES + 2 * X_BYTES + 2 * W_BYTES; // 181248

// interleaved-weight scratch: [branch][t][ ((c4*4+kk)*16 + k4)*4 + cc ]
__device__ __align__(16) float g_wT[3][16][4096];

// ---------------- f32x2 helpers ----------------
__device__ __forceinline__ ULL f2fma(ULL a, ULL b, ULL c) {
    ULL d; asm("fma.rn.f32x2 %0, %1, %2, %3;" : "=l"(d) : "l"(a), "l"(b), "l"(c)); return d;
}
__device__ __forceinline__ ULL f2add(ULL a, ULL b) {
    ULL d; asm("add.rn.f32x2 %0, %1, %2;" : "=l"(d) : "l"(a), "l"(b)); return d;
}
__device__ __forceinline__ ULL f2sub(ULL a, ULL b) {   // a - b
    const ULL NEG1 = 0xBF800000BF800000ULL;
    return f2fma(b, NEG1, a);
}
__device__ __forceinline__ ulonglong2 v2add(ulonglong2 a, ulonglong2 b) {
    ulonglong2 r; r.x = f2add(a.x, b.x); r.y = f2add(a.y, b.y); return r;
}
__device__ __forceinline__ ulonglong2 v2sub(ulonglong2 a, ulonglong2 b) {
    ulonglong2 r; r.x = f2sub(a.x, b.x); r.y = f2sub(a.y, b.y); return r;
}
__device__ __forceinline__ float hsum2(ULL a) {
    float lo = __uint_as_float((unsigned)(a & 0xffffffffu));
    float hi = __uint_as_float((unsigned)(a >> 32));
    return lo + hi;
}

// ---------------- cp.async helpers ----------------
__device__ __forceinline__ void cpa16(void* dst_smem, const void* src) {
    unsigned sdst = (unsigned)__cvta_generic_to_shared(dst_smem);
    asm volatile("cp.async.cg.shared.global [%0], [%1], 16;" :: "r"(sdst), "l"(src));
}
#define CP_COMMIT() asm volatile("cp.async.commit_group;")
#define CP_WAIT1()  asm volatile("cp.async.wait_group 1;")

// ---------------- weight interleave kernel (once per launch, ~1.5 MB traffic) ----
__global__ void wtrans_kernel(const float* __restrict__ w1,
                              const float* __restrict__ w2,
                              const float* __restrict__ w3) {
    int br = blockIdx.x >> 4;
    int t  = blockIdx.x & 15;
    const float* w = (br == 0 ? w1 : (br == 1 ? w2 : w3)) + t * 4096;
    float* dst = g_wT[br][t];
    for (int idx = threadIdx.x; idx < 4096; idx += blockDim.x) {
        int c = idx >> 6, k = idx & 63;          // w is [c][k], coalesced read over k
        int c4 = c >> 2, cc = c & 3, k4 = k >> 2, kk = k & 3;
        dst[((c4 * 4 + kk) * 16 + k4) * 4 + cc] = w[idx];
    }
}

// ---------------- main fused kernel ----------------
__global__ __launch_bounds__(128)
void iwht_kernel(const float* __restrict__ tr1, const float* __restrict__ tr2,
                 const float* __restrict__ tr3,
                 const float* __restrict__ b1, const float* __restrict__ b2,
                 const float* __restrict__ b3,
                 float* __restrict__ out) {
    extern __shared__ char smem[];
    float* ysm  = (float*)smem;                 // [32][16][64] floats
    char*  xbuf = smem + Y_BYTES;               // 2 x [32][68] floats
    char*  wbuf = smem + Y_BYTES + 2 * X_BYTES; // 2 x interleaved [64][64]

    const int tid  = threadIdx.x;
    const int quad = tid >> 4;          // 0..7  -> 4 pixels each
    const int k4   = tid & 15;          // 0..15 -> 4 k each
    const int pb   = quad * 4;

    const int branch = blockIdx.y;
    const float* tr   = (branch == 0 ? tr1 : (branch == 1 ? tr2 : tr3));
    const float* bias = (branch == 0 ? b1  : (branch == 1 ? b2  : b3));
    const int pix0 = blockIdx.x * PIX_T;
    const float* xg = tr + (size_t)pix0 * 64;
    const float* wg = g_wT[branch][0];

    // stage loader: x tile (32x64, padded rows) + interleaved w_t (16KB)
    auto loadT = [&](int t, int buf) {
        char* xb = xbuf + buf * X_BYTES;
        char* wb = wbuf + buf * W_BYTES;
        const float* xs = xg + (size_t)t * T_STRIDE;
        #pragma unroll
        for (int i = 0; i < 4; i++) {           // 512 chunks of 16B
            int ch = tid + i * 128;
            int pix = ch >> 4, seg = ch & 15;
            cpa16(xb + pix * X_PITCH + seg * 16, xs + pix * 64 + seg * 4);
        }
        const float* wsrc = wg + t * 4096;
        #pragma unroll
        for (int i = 0; i < 8; i++) {           // 1024 chunks of 16B
            int ch = tid + i * 128;
            cpa16(wb + ch * 16, wsrc + ch * 4);
        }
    };

    loadT(0, 0); CP_COMMIT();
    loadT(1, 1); CP_COMMIT();

    for (int t = 0; t < 16; t++) {
        CP_WAIT1();
        __syncthreads();
        const char* xb = xbuf + (t & 1) * X_BYTES;
        const char* wb = wbuf + (t & 1) * W_BYTES;

        ULL acc[4][4] = {};
        #pragma unroll
        for (int c4 = 0; c4 < 16; c4++) {
            ulonglong2 xv[4], wv[4];
            #pragma unroll
            for (int p = 0; p < 4; p++)
                xv[p] = *(const ulonglong2*)(xb + (pb + p) * X_PITCH + c4 * 16);
            #pragma unroll
            for (int kk = 0; kk < 4; kk++)
                wv[kk] = *(const ulonglong2*)(wb + (((c4 << 2) + kk) << 8) + (k4 << 4));
            #pragma unroll
            for (int p = 0; p < 4; p++)
                #pragma unroll
                for (int kk = 0; kk < 4; kk++) {
                    acc[p][kk] = f2fma(xv[p].x, wv[kk].x, acc[p][kk]);
                    acc[p][kk] = f2fma(xv[p].y, wv[kk].y, acc[p][kk]);
                }
        }
        // reduce packed lanes and park y_t in smem
        #pragma unroll
        for (int p = 0; p < 4; p++) {
            float4 yo;
            yo.x = hsum2(acc[p][0]); yo.y = hsum2(acc[p][1]);
            yo.z = hsum2(acc[p][2]); yo.w = hsum2(acc[p][3]);
            *(float4*)(ysm + ((pb + p) * 16 + t) * 64 + (k4 << 2)) = yo;
        }
        __syncthreads();
        int tn = t + 2;
        if (tn < 16) loadT(tn, t & 1);
        CP_COMMIT();                            // empty groups at tail keep counts aligned
    }

    __syncthreads();

    // ---------------- epilogue: 2D inverse WHT (butterflies) + bias + store ----
    const ULL SC = 0x3D8000003D800000ULL;       // (1/16, 1/16)
    float* outB = out + (size_t)branch * OUT_PER_BRANCH;

    #pragma unroll
    for (int it = 0; it < 4; it++) {
        int unit = it * 128 + tid;
        int pix = unit >> 4, kq = unit & 15;

        ulonglong2 Y[16];
        #pragma unroll
        for (int t = 0; t < 16; t++)
            Y[t] = *(const ulonglong2*)(ysm + (pix * 16 + t) * 64 + (kq << 2));

        // u-stage: U[p][v] = sum_u H[p][u] Y[4u+v]
        ulonglong2 U[4][4];
        #pragma unroll
        for (int v = 0; v < 4; v++) {
            ulonglong2 s0 = v2add(Y[v],     Y[8 + v]);
            ulonglong2 s1 = v2add(Y[4 + v], Y[12 + v]);
            ulonglong2 d0 = v2sub(Y[v],     Y[8 + v]);
            ulonglong2 d1 = v2sub(Y[4 + v], Y[12 + v]);
            U[0][v] = v2add(s0, s1); U[1][v] = v2sub(s0, s1);
            U[2][v] = v2add(d0, d1); U[3][v] = v2sub(d0, d1);
        }

        int P = pix0 + pix;
        int b = P / 784, r = P % 784;
        int i = r / 28, j = r % 28;
        ulonglong2 bb = *(const ulonglong2*)(bias + (kq << 2));
        float* o0 = outB + ((size_t)(b * 112 + i * 4) * 112 + j * 4) * 64 + (kq << 2);

        #pragma unroll
        for (int p = 0; p < 4; p++) {
            ulonglong2 s0 = v2add(U[p][0], U[p][2]);
            ulonglong2 s1 = v2add(U[p][1], U[p][3]);
            ulonglong2 d0 = v2sub(U[p][0], U[p][2]);
            ulonglong2 d1 = v2sub(U[p][1], U[p][3]);
            ulonglong2 Z[4];
            Z[0] = v2add(s0, s1); Z[1] = v2sub(s0, s1);
            Z[2] = v2add(d0, d1); Z[3] = v2sub(d0, d1);
            float* orow = o0 + p * 112 * 64;
            #pragma unroll
            for (int q = 0; q < 4; q++) {
                ulonglong2 o;
                o.x = f2fma(Z[q].x, SC, bb.x);
                o.y = f2fma(Z[q].y, SC, bb.y);
                *(ulonglong2*)(orow + q * 64) = o;
            }
        }
    }
}

// ---------------- launch ----------------
extern "C" void kernel_launch(void* const* d_in, const int* in_sizes, int n_in,
                              void* d_out, int out_size) {
    (void)in_sizes; (void)n_in; (void)out_size;
    const float* tr1 = (const float*)d_in[0];
    const float* tr2 = (const float*)d_in[1];
    const float* tr3 = (const float*)d_in[2];
    const float* w1  = (const float*)d_in[3];
    const float* w2  = (const float*)d_in[4];
    const float* w3  = (const float*)d_in[5];
    const float* b1  = (const float*)d_in[6];
    const float* b2  = (const float*)d_in[7];
    const float* b3  = (const float*)d_in[8];
    float* out = (float*)d_out;

    cudaFuncSetAttribute(iwht_kernel, cudaFuncAttributeMaxDynamicSharedMemorySize,
                         SMEM_BYTES);

    wtrans_kernel<<<48, 256>>>(w1, w2, w3);
    dim3 grid(NBLK, 3);
    iwht_kernel<<<grid, 128, SMEM_BYTES>>>(tr1, tr2, tr3, b1, b2, b3, out);
}